// round 16
// baseline (speedup 1.0000x reference)
#include <cuda_runtime.h>
#include <cuda_fp16.h>
#include <math_constants.h>
#include <cstdint>

#define D_MODEL 1024
#define NUM_HEADS 16
#define HEAD_DIM 64
#define BATCH 2
#define SEQ 2048
#define PHI_F 8
#define MTOT (BATCH * SEQ)   // 4096
#define LOG2E 1.4426950408889634f

// ---------------- scratch (device globals, no runtime allocation) ------------
__device__ __half g_hWq[D_MODEL * D_MODEL];
__device__ __half g_hWk[D_MODEL * D_MODEL];
__device__ __half g_hWv[D_MODEL * D_MODEL];
__device__ __half g_hWo[D_MODEL * D_MODEL];
__device__ __half g_hq[MTOT * D_MODEL];
__device__ __half g_hk[MTOT * D_MODEL];
__device__ __half g_hv[MTOT * D_MODEL];
__device__ __half g_hattn[MTOT * D_MODEL];

// ======================= small helpers =======================================
__device__ __forceinline__ uint32_t cvta_shared_u32(const void* p) {
    uint32_t a;
    asm("{ .reg .u64 t; cvta.to.shared.u64 t, %1; cvt.u32.u64 %0, t; }"
        : "=r"(a) : "l"(p));
    return a;
}
__device__ __forceinline__ void cpa16(uint32_t s, const void* g) {
    asm volatile("cp.async.cg.shared.global [%0], [%1], 16;\n" :: "r"(s), "l"(g));
}
#define CP_COMMIT() asm volatile("cp.async.commit_group;\n" ::: "memory")
#define CP_WAIT(n)  asm volatile("cp.async.wait_group %0;\n" :: "n"(n) : "memory")

__device__ __forceinline__ void ldsm_x4(uint32_t* r, uint32_t addr) {
    asm volatile("ldmatrix.sync.aligned.m8n8.x4.shared.b16 {%0,%1,%2,%3}, [%4];"
                 : "=r"(r[0]), "=r"(r[1]), "=r"(r[2]), "=r"(r[3]) : "r"(addr));
}
__device__ __forceinline__ void ldsm_x4_t(uint32_t* r, uint32_t addr) {
    asm volatile("ldmatrix.sync.aligned.m8n8.x4.trans.shared.b16 {%0,%1,%2,%3}, [%4];"
                 : "=r"(r[0]), "=r"(r[1]), "=r"(r[2]), "=r"(r[3]) : "r"(addr));
}
__device__ __forceinline__ void mma16816(float* d, const uint32_t* a,
                                         uint32_t b0, uint32_t b1) {
    asm volatile(
        "mma.sync.aligned.m16n8k16.row.col.f32.f16.f16.f32 "
        "{%0,%1,%2,%3}, {%4,%5,%6,%7}, {%8,%9}, {%0,%1,%2,%3};"
        : "+f"(d[0]), "+f"(d[1]), "+f"(d[2]), "+f"(d[3])
        : "r"(a[0]), "r"(a[1]), "r"(a[2]), "r"(a[3]), "r"(b0), "r"(b1));
}
__device__ __forceinline__ uint32_t pack_h2(float x, float y) {
    __half2 h = __floats2half2_rn(x, y);
    return *reinterpret_cast<uint32_t*>(&h);
}
__device__ __forceinline__ float ex2(float x) {
    float y;
    asm("ex2.approx.ftz.f32 %0, %1;" : "=f"(y) : "f"(x));
    return y;
}

// ---------------- fp32 -> fp16 conversion: WEIGHTS ONLY ----------------------
__global__ void f2h4(const float4* __restrict__ s0, const float4* __restrict__ s1,
                     const float4* __restrict__ s2, const float4* __restrict__ s3,
                     uint4* __restrict__ d0, uint4* __restrict__ d1,
                     uint4* __restrict__ d2, uint4* __restrict__ d3, int n8) {
    const float4* s = (blockIdx.y == 0) ? s0 : (blockIdx.y == 1) ? s1
                     : (blockIdx.y == 2) ? s2 : s3;
    uint4* d = (blockIdx.y == 0) ? d0 : (blockIdx.y == 1) ? d1
              : (blockIdx.y == 2) ? d2 : d3;
    int i = blockIdx.x * blockDim.x + threadIdx.x;
    if (i < n8) {
        float4 x = s[2 * i], y = s[2 * i + 1];
        uint4 o;
        o.x = pack_h2(x.x, x.y); o.y = pack_h2(x.z, x.w);
        o.z = pack_h2(y.x, y.y); o.w = pack_h2(y.z, y.w);
        d[i] = o;
    }
}

// ============== shared GEMM constants ========================================
#define GS 40                        // fp16 smem row stride in halfs (80B)
#define GSTG (128 * GS)              // halfs per fp16 matrix per stage (5120)

// ============== QKV GEMM with fused fp32->fp16 A conversion ==================
// A arrives fp32 via 3-stage cp.async ring; converted in-smem to a single
// fp16 ldsm buffer each iter. W is pre-converted fp16 (3-stage ring).
// Layout (bytes): stage st at st*Q_STGB: [A32: 128x36 floats = 18432][W16: 128x40 halfs = 10240]
// Ah fp16 buffer at 3*Q_STGB, 10240 bytes.
#define Q_A32B (128 * 36 * 4)        // 18432
#define Q_STGB (Q_A32B + GSTG * 2)   // 28672
#define Q_SMEM (3 * Q_STGB + GSTG * 2)  // 96256

__global__ __launch_bounds__(256, 2)
void gemm_qkv(const float* __restrict__ A0, const float* __restrict__ A1,
              const float* __restrict__ A2,
              const __half* __restrict__ W0, const __half* __restrict__ W1,
              const __half* __restrict__ W2,
              const float* __restrict__ b0, const float* __restrict__ b1,
              const float* __restrict__ b2,
              __half* __restrict__ C0, __half* __restrict__ C1,
              __half* __restrict__ C2) {
    extern __shared__ char qsm[];

    const int z = blockIdx.z;
    const float* A = (z == 0) ? A0 : (z == 1) ? A1 : A2;
    const __half* W = (z == 0) ? W0 : (z == 1) ? W1 : W2;
    const float* bias = (z == 0) ? b0 : (z == 1) ? b1 : b2;
    __half* C = (z == 0) ? C0 : (z == 1) ? C1 : C2;

    const int tid = threadIdx.x;
    const int wid = tid >> 5, lane = tid & 31;
    const int gid = lane >> 2, tig = lane & 3;
    const int bm = blockIdx.y * 128;
    const int bn = blockIdx.x * 128;
    const uint32_t s0 = cvta_shared_u32(qsm);
    const uint32_t ah0 = s0 + 3u * Q_STGB;

    // loader: A fp32 (row = tid>>1, 16 floats at (tid&1)*16), W fp16 (as proven)
    const int arow = tid >> 1, acol = (tid & 1) * 16;
    const int lrow = tid >> 2, lkc = (tid & 3) * 8;

    auto load_stage = [&](int kt, int st) {
        const int k0 = kt * 32;
        uint32_t abase = s0 + (uint32_t)(st * Q_STGB);
        const float* Ag = A + (size_t)(bm + arow) * D_MODEL + k0 + acol;
#pragma unroll
        for (int i = 0; i < 4; ++i)
            cpa16(abase + (uint32_t)(arow * 144 + (acol + i * 4) * 4), Ag + i * 4);
        uint32_t wbase = abase + Q_A32B;
#pragma unroll
        for (int i = 0; i < 2; ++i) {
            int row = lrow + i * 64;
            cpa16(wbase + (uint32_t)(row * GS + lkc) * 2,
                  W + (size_t)(bn + row) * D_MODEL + k0 + lkc);
        }
        CP_COMMIT();
    };

    float acc[2][8][4];
#pragma unroll
    for (int m = 0; m < 2; ++m)
#pragma unroll
        for (int n = 0; n < 8; ++n)
#pragma unroll
            for (int k = 0; k < 4; ++k) acc[m][n][k] = 0.f;

    const int sub = lane >> 3, r = lane & 7;
    const int aRow = (wid & 3) * 32 + ((sub & 1) ? 8 : 0) + r;
    const int aCol = (sub & 2) ? 8 : 0;
    const int bRow = (wid >> 2) * 64 + ((sub & 2) ? 8 : 0) + r;
    const int bCol = (sub & 1) ? 8 : 0;
    const uint32_t aBase = ah0 + (uint32_t)(aRow * GS + aCol) * 2;

    load_stage(0, 0);
    load_stage(1, 1);

    const int NT = D_MODEL / 32;     // 32
    for (int kt = 0; kt < NT; ++kt) {
        const int st = kt % 3;
        if (kt < NT - 1) CP_WAIT(1); else CP_WAIT(0);
        __syncthreads();                       // BAR1: stage kt ready; stage (kt+2)%3 free
        if (kt + 2 < NT) load_stage(kt + 2, (kt + 2) % 3);

        // convert A fp32 -> fp16 ldsm buffer (same rn as f2h: bit-identical)
        {
            uint32_t asrc = s0 + (uint32_t)(st * Q_STGB) + (uint32_t)(arow * 144 + acol * 4);
            float4 v0 = *(const float4*)(qsm + (asrc - s0));
            float4 v1 = *(const float4*)(qsm + (asrc - s0) + 16);
            float4 v2 = *(const float4*)(qsm + (asrc - s0) + 32);
            float4 v3 = *(const float4*)(qsm + (asrc - s0) + 48);
            uint4 h0, h1;
            h0.x = pack_h2(v0.x, v0.y); h0.y = pack_h2(v0.z, v0.w);
            h0.z = pack_h2(v1.x, v1.y); h0.w = pack_h2(v1.z, v1.w);
            h1.x = pack_h2(v2.x, v2.y); h1.y = pack_h2(v2.z, v2.w);
            h1.z = pack_h2(v3.x, v3.y); h1.w = pack_h2(v3.z, v3.w);
            char* adst = qsm + 3 * Q_STGB + (arow * GS + acol) * 2;
            *(uint4*)adst = h0;
            *(uint4*)(adst + 16) = h1;
        }
        __syncthreads();                       // BAR2: Ah ready

        const uint32_t bBase = s0 + (uint32_t)(st * Q_STGB) + Q_A32B
                             + (uint32_t)(bRow * GS + bCol) * 2;
#pragma unroll
        for (int ks = 0; ks < 2; ++ks) {
            uint32_t af[2][4];
            ldsm_x4(af[0], aBase + (uint32_t)(ks * 16) * 2);
            ldsm_x4(af[1], aBase + (uint32_t)(16 * GS + ks * 16) * 2);
#pragma unroll
            for (int np = 0; np < 4; ++np) {
                uint32_t bf[4];
                ldsm_x4(bf, bBase + (uint32_t)(np * 16 * GS + ks * 16) * 2);
#pragma unroll
                for (int m = 0; m < 2; ++m) {
                    mma16816(acc[m][2 * np + 0], af[m], bf[0], bf[1]);
                    mma16816(acc[m][2 * np + 1], af[m], bf[2], bf[3]);
                }
            }
        }
    }

#pragma unroll
    for (int m = 0; m < 2; ++m) {
        int row0 = bm + (wid & 3) * 32 + m * 16 + gid;
#pragma unroll
        for (int n = 0; n < 8; ++n) {
            int col = bn + (wid >> 2) * 64 + n * 8 + 2 * tig;
            float b0v = bias[col], b1v = bias[col + 1];
            __half2* p0 = (__half2*)(C + (size_t)row0 * D_MODEL + col);
            __half2* p1 = (__half2*)(C + (size_t)(row0 + 8) * D_MODEL + col);
            *p0 = __floats2half2_rn(acc[m][n][0] + b0v, acc[m][n][1] + b1v);
            *p1 = __floats2half2_rn(acc[m][n][2] + b0v, acc[m][n][3] + b1v);
        }
    }
}

// ============== output GEMM (R11-proven 4-stage core, fp16 in / fp32 out) ====
#define GSTAGES 4
#define G_SMEM (GSTAGES * 2 * GSTG * 2)   // 81920 bytes

__global__ __launch_bounds__(256, 2)
void gemm_out(const __half* __restrict__ A, const __half* __restrict__ W,
              const float* __restrict__ bias, float* __restrict__ C) {
    extern __shared__ __half gsm[];

    const int tid = threadIdx.x;
    const int wid = tid >> 5, lane = tid & 31;
    const int gid = lane >> 2, tig = lane & 3;
    const int bm = blockIdx.y * 128;
    const int bn = blockIdx.x * 128;
    const uint32_t s0 = cvta_shared_u32(gsm);

    const int lrow = tid >> 2, lkc = (tid & 3) * 8;

    auto load_stage = [&](int kt, int st) {
        const int k0 = kt * 32;
        uint32_t base = s0 + (uint32_t)(st * 2 * GSTG) * 2;
#pragma unroll
        for (int i = 0; i < 2; ++i) {
            int row = lrow + i * 64;
            cpa16(base + (uint32_t)(row * GS + lkc) * 2,
                  A + (size_t)(bm + row) * D_MODEL + k0 + lkc);
            cpa16(base + (uint32_t)(GSTG + row * GS + lkc) * 2,
                  W + (size_t)(bn + row) * D_MODEL + k0 + lkc);
        }
        CP_COMMIT();
    };

    float acc[2][8][4];
#pragma unroll
    for (int m = 0; m < 2; ++m)
#pragma unroll
        for (int n = 0; n < 8; ++n)
#pragma unroll
            for (int k = 0; k < 4; ++k) acc[m][n][k] = 0.f;

    const int sub = lane >> 3, r = lane & 7;
    const int aRow = (wid & 3) * 32 + ((sub & 1) ? 8 : 0) + r;
    const int aCol = (sub & 2) ? 8 : 0;
    const int bRow = (wid >> 2) * 64 + ((sub & 2) ? 8 : 0) + r;
    const int bCol = (sub & 1) ? 8 : 0;

    load_stage(0, 0);
    load_stage(1, 1);
    load_stage(2, 2);

    const int NT = D_MODEL / 32;
    for (int kt = 0; kt < NT; ++kt) {
        const int st = kt & 3;
        if (kt < NT - 2)       CP_WAIT(2);
        else if (kt == NT - 2) CP_WAIT(1);
        else                   CP_WAIT(0);
        __syncthreads();
        if (kt + 3 < NT) load_stage(kt + 3, (kt + 3) & 3);

        const uint32_t aBase = s0 + (uint32_t)(st * 2 * GSTG + aRow * GS + aCol) * 2;
        const uint32_t bBase = s0 + (uint32_t)(st * 2 * GSTG + GSTG + bRow * GS + bCol) * 2;
#pragma unroll
        for (int ks = 0; ks < 2; ++ks) {
            uint32_t af[2][4];
            ldsm_x4(af[0], aBase + (uint32_t)(ks * 16) * 2);
            ldsm_x4(af[1], aBase + (uint32_t)(16 * GS + ks * 16) * 2);
#pragma unroll
            for (int np = 0; np < 4; ++np) {
                uint32_t bf[4];
                ldsm_x4(bf, bBase + (uint32_t)(np * 16 * GS + ks * 16) * 2);
#pragma unroll
                for (int m = 0; m < 2; ++m) {
                    mma16816(acc[m][2 * np + 0], af[m], bf[0], bf[1]);
                    mma16816(acc[m][2 * np + 1], af[m], bf[2], bf[3]);
                }
            }
        }
    }

#pragma unroll
    for (int m = 0; m < 2; ++m) {
        int row0 = bm + (wid & 3) * 32 + m * 16 + gid;
#pragma unroll
        for (int n = 0; n < 8; ++n) {
            int col = bn + (wid >> 2) * 64 + n * 8 + 2 * tig;
            float b0v = bias[col], b1v = bias[col + 1];
            float2* p0 = (float2*)(C + (size_t)row0 * D_MODEL + col);
            float2* p1 = (float2*)(C + (size_t)(row0 + 8) * D_MODEL + col);
            *p0 = make_float2(acc[m][n][0] + b0v, acc[m][n][1] + b1v);
            *p1 = make_float2(acc[m][n][2] + b0v, acc[m][n][3] + b1v);
        }
    }
}

// ============== fp16 mma flash attention (R11 + vote-skip rescale) ===========
#define FBQ 128
#define FBK 64
#define FS 72
#define FST (FBK * FS)
#define FNT (SEQ / FBK)
#define F_SMEM ((FBQ * FS + 6 * FST) * 2)

__global__ __launch_bounds__(256)
void flash_h(const __half* __restrict__ Q, const __half* __restrict__ K,
             const __half* __restrict__ V, const float* __restrict__ phi,
             __half* __restrict__ O) {
    extern __shared__ __half fsm[];
    __half* Qs = fsm;
    __half* Ks = Qs + FBQ * FS;
    __half* Vs = Ks + 3 * FST;

    const int tid = threadIdx.x;
    const int wid = tid >> 5, lane = tid & 31;
    const int gid = lane >> 2, tig = lane & 3;
    const int b = blockIdx.z, h = blockIdx.y;
    const int q0 = blockIdx.x * FBQ;

    const uint32_t qs0 = cvta_shared_u32(Qs);
    const uint32_t ks0 = cvta_shared_u32(Ks);
    const uint32_t vs0 = cvta_shared_u32(Vs);

    auto load_q = [&]() {
#pragma unroll
        for (int i = 0; i < 4; ++i) {
            int idx = tid + i * 256;
            int row = idx >> 3, kc = (idx & 7) * 8;
            cpa16(qs0 + (uint32_t)(row * FS + kc) * 2,
                  Q + (size_t)(b * SEQ + q0 + row) * D_MODEL + h * HEAD_DIM + kc);
        }
    };
    auto load_kv = [&](int kt, int st) {
        const int k0 = kt * FBK;
#pragma unroll
        for (int i = 0; i < 2; ++i) {
            int idx = tid + i * 256;
            int row = idx >> 3, kc = (idx & 7) * 8;
            size_t g = (size_t)(b * SEQ + k0 + row) * D_MODEL + h * HEAD_DIM + kc;
            cpa16(ks0 + (uint32_t)(st * FST + row * FS + kc) * 2, K + g);
            cpa16(vs0 + (uint32_t)(st * FST + row * FS + kc) * 2, V + g);
        }
        CP_COMMIT();
    };

    load_q();
    load_kv(0, 0);
    load_kv(1, 1);

    const int rowA = q0 + wid * 16 + gid;
    float qsA, qsB;
    {
        const float4* p0 = (const float4*)&phi[(size_t)(b * SEQ + rowA) * PHI_F];
        const float4* p1 = (const float4*)&phi[(size_t)(b * SEQ + rowA + 8) * PHI_F];
        float4 a0 = p0[0], a1 = p0[1], b0 = p1[0], b1 = p1[1];
        float sA = (a0.x + a0.y + a0.z + a0.w + a1.x + a1.y + a1.z + a1.w) * (1.0f / PHI_F);
        float sB = (b0.x + b0.y + b0.z + b0.w + b1.x + b1.y + b1.z + b1.w) * (1.0f / PHI_F);
        qsA = LOG2E / (8.0f * fmaxf(sA, 1e-6f));
        qsB = LOG2E / (8.0f * fmaxf(sB, 1e-6f));
    }

    float mA = -CUDART_INF_F, mB = -CUDART_INF_F;
    float lA = 0.f, lB = 0.f;
    float o[8][4];
#pragma unroll
    for (int d = 0; d < 8; ++d)
#pragma unroll
        for (int k = 0; k < 4; ++k) o[d][k] = 0.f;

    const int sub = lane >> 3, r = lane & 7;
    const int kRow = ((sub & 2) ? 8 : 0) + r, kCol = (sub & 1) ? 8 : 0;
    const int vRow = ((sub & 1) ? 8 : 0) + r, vCol = (sub & 2) ? 8 : 0;

    CP_WAIT(1);
    __syncthreads();

    uint32_t qf[4][4];
    {
        const int qRow = wid * 16 + ((sub & 1) ? 8 : 0) + r;
        const int qCol = (sub & 2) ? 8 : 0;
        uint32_t base = qs0 + (uint32_t)(qRow * FS + qCol) * 2;
#pragma unroll
        for (int ks = 0; ks < 4; ++ks) ldsm_x4(qf[ks], base + (uint32_t)(ks * 16) * 2);
    }

    for (int kt = 0; kt < FNT; ++kt) {
        const int st = kt % 3;
        if (kt > 0) {
            if (kt < FNT - 1) CP_WAIT(1); else CP_WAIT(0);
            __syncthreads();
        }
        if (kt + 2 < FNT) load_kv(kt + 2, (kt + 2) % 3);

        // ---- S = Q K^T (raw scores) ----
        float s[8][4];
#pragma unroll
        for (int n = 0; n < 8; ++n)
#pragma unroll
            for (int k = 0; k < 4; ++k) s[n][k] = 0.f;

        const uint32_t kBase = ks0 + (uint32_t)(st * FST + kRow * FS + kCol) * 2;
#pragma unroll
        for (int ks = 0; ks < 4; ++ks) {
#pragma unroll
            for (int np = 0; np < 4; ++np) {
                uint32_t bf[4];
                ldsm_x4(bf, kBase + (uint32_t)(np * 16 * FS + ks * 16) * 2);
                mma16816(s[2 * np + 0], qf[ks], bf[0], bf[1]);
                mma16816(s[2 * np + 1], qf[ks], bf[2], bf[3]);
            }
        }

        // ---- online softmax: max on RAW scores ----
        float tA = -CUDART_INF_F, tB = -CUDART_INF_F;
#pragma unroll
        for (int n = 0; n < 8; ++n) {
            tA = fmaxf(tA, fmaxf(s[n][0], s[n][1]));
            tB = fmaxf(tB, fmaxf(s[n][2], s[n][3]));
        }
        tA = fmaxf(tA, __shfl_xor_sync(0xffffffffu, tA, 1));
        tA = fmaxf(tA, __shfl_xor_sync(0xffffffffu, tA, 2));
        tB = fmaxf(tB, __shfl_xor_sync(0xffffffffu, tB, 1));
        tB = fmaxf(tB, __shfl_xor_sync(0xffffffffu, tB, 2));

        float mAn = fmaxf(mA, tA * qsA), mBn = fmaxf(mB, tB * qsB);
        const bool changed = (mAn > mA) || (mBn > mB);
        const bool any_changed = __any_sync(0xffffffffu, changed);

        if (any_changed) {
            float cA = ex2(mA - mAn), cB = ex2(mB - mBn);
            mA = mAn; mB = mBn;
            lA *= cA; lB *= cB;
#pragma unroll
            for (int d = 0; d < 8; ++d) {
                o[d][0] *= cA; o[d][1] *= cA;
                o[d][2] *= cB; o[d][3] *= cB;
            }
        }

        // exp2(s*qs - m) via FFMA + MUFU; deferred row sums
        float sumA = 0.f, sumB = 0.f;
#pragma unroll
        for (int n = 0; n < 8; ++n) {
            s[n][0] = ex2(fmaf(s[n][0], qsA, -mA));
            s[n][1] = ex2(fmaf(s[n][1], qsA, -mA));
            s[n][2] = ex2(fmaf(s[n][2], qsB, -mB));
            s[n][3] = ex2(fmaf(s[n][3], qsB, -mB));
            sumA += s[n][0] + s[n][1];
            sumB += s[n][2] + s[n][3];
        }
        lA += sumA;
        lB += sumB;

        // ---- O += P V ----
        const uint32_t vBase = vs0 + (uint32_t)(st * FST + vRow * FS + vCol) * 2;
#pragma unroll
        for (int ks = 0; ks < 4; ++ks) {
            uint32_t pa[4];
            pa[0] = pack_h2(s[2 * ks][0], s[2 * ks][1]);
            pa[1] = pack_h2(s[2 * ks][2], s[2 * ks][3]);
            pa[2] = pack_h2(s[2 * ks + 1][0], s[2 * ks + 1][1]);
            pa[3] = pack_h2(s[2 * ks + 1][2], s[2 * ks + 1][3]);
#pragma unroll
            for (int dp = 0; dp < 4; ++dp) {
                uint32_t bf[4];
                ldsm_x4_t(bf, vBase + (uint32_t)(ks * 16 * FS + dp * 16) * 2);
                mma16816(o[2 * dp + 0], pa, bf[0], bf[1]);
                mma16816(o[2 * dp + 1], pa, bf[2], bf[3]);
            }
        }
    }

    lA += __shfl_xor_sync(0xffffffffu, lA, 1);
    lA += __shfl_xor_sync(0xffffffffu, lA, 2);
    lB += __shfl_xor_sync(0xffffffffu, lB, 1);
    lB += __shfl_xor_sync(0xffffffffu, lB, 2);

    const float iA = 1.0f / lA, iB = 1.0f / lB;
#pragma unroll
    for (int d = 0; d < 8; ++d) {
        int col = h * HEAD_DIM + d * 8 + 2 * tig;
        __half2* p0 = (__half2*)(O + (size_t)(b * SEQ + rowA) * D_MODEL + col);
        __half2* p1 = (__half2*)(O + (size_t)(b * SEQ + rowA + 8) * D_MODEL + col);
        *p0 = __floats2half2_rn(o[d][0] * iA, o[d][1] * iA);
        *p1 = __floats2half2_rn(o[d][2] * iB, o[d][3] * iB);
    }
}

// ---------------- launch ------------------------------------------------------
extern "C" void kernel_launch(void* const* d_in, const int* in_sizes, int n_in,
                              void* d_out, int out_size) {
    const float* query = (const float*)d_in[0];
    const float* key   = (const float*)d_in[1];
    const float* value = (const float*)d_in[2];
    const float* phi   = (const float*)d_in[3];
    const float* Wq = (const float*)d_in[5];
    const float* bq = (const float*)d_in[6];
    const float* Wk = (const float*)d_in[7];
    const float* bk = (const float*)d_in[8];
    const float* Wv = (const float*)d_in[9];
    const float* bv = (const float*)d_in[10];
    const float* Wo = (const float*)d_in[11];
    const float* bo = (const float*)d_in[12];
    float* out = (float*)d_out;

    __half *hWq, *hWk, *hWv, *hWo, *hq, *hk, *hv, *hattn;
    cudaGetSymbolAddress((void**)&hWq, g_hWq);
    cudaGetSymbolAddress((void**)&hWk, g_hWk);
    cudaGetSymbolAddress((void**)&hWv, g_hWv);
    cudaGetSymbolAddress((void**)&hWo, g_hWo);
    cudaGetSymbolAddress((void**)&hq, g_hq);
    cudaGetSymbolAddress((void**)&hk, g_hk);
    cudaGetSymbolAddress((void**)&hv, g_hv);
    cudaGetSymbolAddress((void**)&hattn, g_hattn);

    cudaFuncSetAttribute(gemm_qkv, cudaFuncAttributeMaxDynamicSharedMemorySize, Q_SMEM);
    cudaFuncSetAttribute(gemm_out, cudaFuncAttributeMaxDynamicSharedMemorySize, G_SMEM);
    cudaFuncSetAttribute(flash_h, cudaFuncAttributeMaxDynamicSharedMemorySize, F_SMEM);

    const int nW8 = D_MODEL * D_MODEL / 8;   // 131072

    // weights-only conversion (activations converted inside gemm_qkv)
    f2h4<<<dim3((nW8 + 255) / 256, 4), 256>>>(
        (const float4*)Wq, (const float4*)Wk, (const float4*)Wv, (const float4*)Wo,
        (uint4*)hWq, (uint4*)hWk, (uint4*)hWv, (uint4*)hWo, nW8);

    dim3 qkvgrid(D_MODEL / 128, MTOT / 128, 3);
    gemm_qkv<<<qkvgrid, 256, Q_SMEM>>>(query, key, value, hWq, hWk, hWv,
                                       bq, bk, bv, hq, hk, hv);

    dim3 fgrid(SEQ / FBQ, NUM_HEADS, BATCH);
    flash_h<<<fgrid, 256, F_SMEM>>>(hq, hk, hv, phi, hattn);

    dim3 ggrid(D_MODEL / 128, MTOT / 128);
    gemm_out<<<ggrid, 256, G_SMEM>>>(hattn, hWo, bo, out);
}

// round 17
// speedup vs baseline: 1.2452x; 1.2452x over previous
#include <cuda_runtime.h>
#include <cuda_fp16.h>
#include <math_constants.h>
#include <cstdint>

#define D_MODEL 1024
#define NUM_HEADS 16
#define HEAD_DIM 64
#define BATCH 2
#define SEQ 2048
#define PHI_F 8
#define MTOT (BATCH * SEQ)   // 4096
#define LOG2E 1.4426950408889634f

// ---------------- scratch (device globals, no runtime allocation) ------------
__device__ __half g_hA[MTOT * D_MODEL];      // fp16 query input
__device__ __half g_hB[MTOT * D_MODEL];      // fp16 key input
__device__ __half g_hC[MTOT * D_MODEL];      // fp16 value input
__device__ __half g_hWq[D_MODEL * D_MODEL];
__device__ __half g_hWk[D_MODEL * D_MODEL];
__device__ __half g_hWv[D_MODEL * D_MODEL];
__device__ __half g_hWo[D_MODEL * D_MODEL];
__device__ __half g_hq[MTOT * D_MODEL];
__device__ __half g_hk[MTOT * D_MODEL];
__device__ __half g_hv[MTOT * D_MODEL];
__device__ __half g_hattn[MTOT * D_MODEL];

// ======================= small helpers =======================================
__device__ __forceinline__ uint32_t cvta_shared_u32(const void* p) {
    uint32_t a;
    asm("{ .reg .u64 t; cvta.to.shared.u64 t, %1; cvt.u32.u64 %0, t; }"
        : "=r"(a) : "l"(p));
    return a;
}
__device__ __forceinline__ void cpa16(uint32_t s, const void* g) {
    asm volatile("cp.async.cg.shared.global [%0], [%1], 16;\n" :: "r"(s), "l"(g));
}
#define CP_COMMIT() asm volatile("cp.async.commit_group;\n" ::: "memory")
#define CP_WAIT(n)  asm volatile("cp.async.wait_group %0;\n" :: "n"(n) : "memory")

__device__ __forceinline__ void ldsm_x4(uint32_t* r, uint32_t addr) {
    asm volatile("ldmatrix.sync.aligned.m8n8.x4.shared.b16 {%0,%1,%2,%3}, [%4];"
                 : "=r"(r[0]), "=r"(r[1]), "=r"(r[2]), "=r"(r[3]) : "r"(addr));
}
__device__ __forceinline__ void ldsm_x4_t(uint32_t* r, uint32_t addr) {
    asm volatile("ldmatrix.sync.aligned.m8n8.x4.trans.shared.b16 {%0,%1,%2,%3}, [%4];"
                 : "=r"(r[0]), "=r"(r[1]), "=r"(r[2]), "=r"(r[3]) : "r"(addr));
}
__device__ __forceinline__ void mma16816(float* d, const uint32_t* a,
                                         uint32_t b0, uint32_t b1) {
    asm volatile(
        "mma.sync.aligned.m16n8k16.row.col.f32.f16.f16.f32 "
        "{%0,%1,%2,%3}, {%4,%5,%6,%7}, {%8,%9}, {%0,%1,%2,%3};"
        : "+f"(d[0]), "+f"(d[1]), "+f"(d[2]), "+f"(d[3])
        : "r"(a[0]), "r"(a[1]), "r"(a[2]), "r"(a[3]), "r"(b0), "r"(b1));
}
__device__ __forceinline__ uint32_t pack_h2(float x, float y) {
    __half2 h = __floats2half2_rn(x, y);
    return *reinterpret_cast<uint32_t*>(&h);
}
__device__ __forceinline__ float ex2(float x) {
    float y;
    asm("ex2.approx.ftz.f32 %0, %1;" : "=f"(y) : "f"(x));
    return y;
}

// ---------------- single fused fp32 -> fp16 conversion (7 tensors) -----------
__global__ void f2h7(const float4* __restrict__ w0, const float4* __restrict__ w1,
                     const float4* __restrict__ w2, const float4* __restrict__ w3,
                     const float4* __restrict__ a0, const float4* __restrict__ a1,
                     const float4* __restrict__ a2,
                     uint4* __restrict__ dw0, uint4* __restrict__ dw1,
                     uint4* __restrict__ dw2, uint4* __restrict__ dw3,
                     uint4* __restrict__ da0, uint4* __restrict__ da1,
                     uint4* __restrict__ da2, int nW8, int nA8) {
    const int z = blockIdx.y;
    const float4* s;
    uint4* d;
    int n8;
    switch (z) {
        case 0: s = w0; d = dw0; n8 = nW8; break;
        case 1: s = w1; d = dw1; n8 = nW8; break;
        case 2: s = w2; d = dw2; n8 = nW8; break;
        case 3: s = w3; d = dw3; n8 = nW8; break;
        case 4: s = a0; d = da0; n8 = nA8; break;
        case 5: s = a1; d = da1; n8 = nA8; break;
        default: s = a2; d = da2; n8 = nA8; break;
    }
    int i = blockIdx.x * blockDim.x + threadIdx.x;
    if (i < n8) {
        float4 x = s[2 * i], y = s[2 * i + 1];
        uint4 o;
        o.x = pack_h2(x.x, x.y); o.y = pack_h2(x.z, x.w);
        o.z = pack_h2(y.x, y.y); o.w = pack_h2(y.z, y.w);
        d[i] = o;
    }
}

// ============== fp16 mma GEMM core ===========================================
// 128x128 tile, BK=32 (proven R3 layout), 4-stage cp.async ring,
// SINGLE __syncthreads per K-iter. 8 warps (4x2), warp tile 32x64.
#define GS 40                        // smem row stride in halfs (80B, conflict-free)
#define GSTG (128 * GS)              // halfs per matrix per stage (5120)
#define GSTAGES 4
#define G_SMEM (GSTAGES * 2 * GSTG * 2)   // 81920 bytes

__device__ __forceinline__ void gemm_core(
    const __half* __restrict__ A, const __half* __restrict__ W,
    __half* smem, int bm, int bn, float acc[2][8][4]) {
    const int tid = threadIdx.x;
    const int wid = tid >> 5, lane = tid & 31;
    const uint32_t s0 = cvta_shared_u32(smem);

    const int lrow = tid >> 2, lkc = (tid & 3) * 8;

    auto load_stage = [&](int kt, int st) {
        const int k0 = kt * 32;
        uint32_t base = s0 + (uint32_t)(st * 2 * GSTG) * 2;
#pragma unroll
        for (int i = 0; i < 2; ++i) {
            int row = lrow + i * 64;
            cpa16(base + (uint32_t)(row * GS + lkc) * 2,
                  A + (size_t)(bm + row) * D_MODEL + k0 + lkc);
            cpa16(base + (uint32_t)(GSTG + row * GS + lkc) * 2,
                  W + (size_t)(bn + row) * D_MODEL + k0 + lkc);
        }
        CP_COMMIT();
    };

    const int sub = lane >> 3, r = lane & 7;
    const int aRow = (wid & 3) * 32 + ((sub & 1) ? 8 : 0) + r;
    const int aCol = (sub & 2) ? 8 : 0;
    const int bRow = (wid >> 2) * 64 + ((sub & 2) ? 8 : 0) + r;
    const int bCol = (sub & 1) ? 8 : 0;

    load_stage(0, 0);
    load_stage(1, 1);
    load_stage(2, 2);

    const int NT = D_MODEL / 32;     // 32
    for (int kt = 0; kt < NT; ++kt) {
        const int st = kt & 3;
        if (kt < NT - 2)       CP_WAIT(2);
        else if (kt == NT - 2) CP_WAIT(1);
        else                   CP_WAIT(0);
        __syncthreads();
        // stage (kt+3)%4 was last read at iter kt-1; the barrier above retired it
        if (kt + 3 < NT) load_stage(kt + 3, (kt + 3) & 3);

        const uint32_t aBase = s0 + (uint32_t)(st * 2 * GSTG + aRow * GS + aCol) * 2;
        const uint32_t bBase = s0 + (uint32_t)(st * 2 * GSTG + GSTG + bRow * GS + bCol) * 2;
#pragma unroll
        for (int ks = 0; ks < 2; ++ks) {
            uint32_t af[2][4];
            ldsm_x4(af[0], aBase + (uint32_t)(ks * 16) * 2);
            ldsm_x4(af[1], aBase + (uint32_t)(16 * GS + ks * 16) * 2);
#pragma unroll
            for (int np = 0; np < 4; ++np) {
                uint32_t bf[4];
                ldsm_x4(bf, bBase + (uint32_t)(np * 16 * GS + ks * 16) * 2);
#pragma unroll
                for (int m = 0; m < 2; ++m) {
                    mma16816(acc[m][2 * np + 0], af[m], bf[0], bf[1]);
                    mma16816(acc[m][2 * np + 1], af[m], bf[2], bf[3]);
                }
            }
        }
    }
}

// QKV fused: blockIdx.z selects which projection this CTA computes.
__global__ __launch_bounds__(256, 2)
void gemm_qkv(const __half* __restrict__ A0, const __half* __restrict__ A1,
              const __half* __restrict__ A2,
              const __half* __restrict__ W0, const __half* __restrict__ W1,
              const __half* __restrict__ W2,
              const float* __restrict__ b0, const float* __restrict__ b1,
              const float* __restrict__ b2,
              __half* __restrict__ C0, __half* __restrict__ C1,
              __half* __restrict__ C2) {
    extern __shared__ __half gsm[];

    const int z = blockIdx.z;
    const __half* A = (z == 0) ? A0 : (z == 1) ? A1 : A2;
    const __half* W = (z == 0) ? W0 : (z == 1) ? W1 : W2;
    const float* bias = (z == 0) ? b0 : (z == 1) ? b1 : b2;
    __half* C = (z == 0) ? C0 : (z == 1) ? C1 : C2;

    const int tid = threadIdx.x;
    const int wid = tid >> 5, lane = tid & 31;
    const int gid = lane >> 2, tig = lane & 3;
    const int bm = blockIdx.y * 128;
    const int bn = blockIdx.x * 128;

    float acc[2][8][4];
#pragma unroll
    for (int m = 0; m < 2; ++m)
#pragma unroll
        for (int n = 0; n < 8; ++n)
#pragma unroll
            for (int k = 0; k < 4; ++k) acc[m][n][k] = 0.f;

    gemm_core(A, W, gsm, bm, bn, acc);

#pragma unroll
    for (int m = 0; m < 2; ++m) {
        int row0 = bm + (wid & 3) * 32 + m * 16 + gid;
#pragma unroll
        for (int n = 0; n < 8; ++n) {
            int col = bn + (wid >> 2) * 64 + n * 8 + 2 * tig;
            float b0v = bias[col], b1v = bias[col + 1];
            __half2* p0 = (__half2*)(C + (size_t)row0 * D_MODEL + col);
            __half2* p1 = (__half2*)(C + (size_t)(row0 + 8) * D_MODEL + col);
            *p0 = __floats2half2_rn(acc[m][n][0] + b0v, acc[m][n][1] + b1v);
            *p1 = __floats2half2_rn(acc[m][n][2] + b0v, acc[m][n][3] + b1v);
        }
    }
}

// Output projection: fp32 out.
__global__ __launch_bounds__(256, 2)
void gemm_out(const __half* __restrict__ A, const __half* __restrict__ W,
              const float* __restrict__ bias, float* __restrict__ C) {
    extern __shared__ __half gsm[];

    const int tid = threadIdx.x;
    const int wid = tid >> 5, lane = tid & 31;
    const int gid = lane >> 2, tig = lane & 3;
    const int bm = blockIdx.y * 128;
    const int bn = blockIdx.x * 128;

    float acc[2][8][4];
#pragma unroll
    for (int m = 0; m < 2; ++m)
#pragma unroll
        for (int n = 0; n < 8; ++n)
#pragma unroll
            for (int k = 0; k < 4; ++k) acc[m][n][k] = 0.f;

    gemm_core(A, W, gsm, bm, bn, acc);

#pragma unroll
    for (int m = 0; m < 2; ++m) {
        int row0 = bm + (wid & 3) * 32 + m * 16 + gid;
#pragma unroll
        for (int n = 0; n < 8; ++n) {
            int col = bn + (wid >> 2) * 64 + n * 8 + 2 * tig;
            float b0v = bias[col], b1v = bias[col + 1];
            float2* p0 = (float2*)(C + (size_t)row0 * D_MODEL + col);
            float2* p1 = (float2*)(C + (size_t)(row0 + 8) * D_MODEL + col);
            *p0 = make_float2(acc[m][n][0] + b0v, acc[m][n][1] + b1v);
            *p1 = make_float2(acc[m][n][2] + b0v, acc[m][n][3] + b1v);
        }
    }
}

// ============== fp16 mma flash attention (R11 + vote-skip rescale) ===========
#define FBQ 128
#define FBK 64
#define FS 72
#define FST (FBK * FS)
#define FNT (SEQ / FBK)
#define F_SMEM ((FBQ * FS + 6 * FST) * 2)

__global__ __launch_bounds__(256)
void flash_h(const __half* __restrict__ Q, const __half* __restrict__ K,
             const __half* __restrict__ V, const float* __restrict__ phi,
             __half* __restrict__ O) {
    extern __shared__ __half fsm[];
    __half* Qs = fsm;
    __half* Ks = Qs + FBQ * FS;
    __half* Vs = Ks + 3 * FST;

    const int tid = threadIdx.x;
    const int wid = tid >> 5, lane = tid & 31;
    const int gid = lane >> 2, tig = lane & 3;
    const int b = blockIdx.z, h = blockIdx.y;
    const int q0 = blockIdx.x * FBQ;

    const uint32_t qs0 = cvta_shared_u32(Qs);
    const uint32_t ks0 = cvta_shared_u32(Ks);
    const uint32_t vs0 = cvta_shared_u32(Vs);

    auto load_q = [&]() {
#pragma unroll
        for (int i = 0; i < 4; ++i) {
            int idx = tid + i * 256;
            int row = idx >> 3, kc = (idx & 7) * 8;
            cpa16(qs0 + (uint32_t)(row * FS + kc) * 2,
                  Q + (size_t)(b * SEQ + q0 + row) * D_MODEL + h * HEAD_DIM + kc);
        }
    };
    auto load_kv = [&](int kt, int st) {
        const int k0 = kt * FBK;
#pragma unroll
        for (int i = 0; i < 2; ++i) {
            int idx = tid + i * 256;
            int row = idx >> 3, kc = (idx & 7) * 8;
            size_t g = (size_t)(b * SEQ + k0 + row) * D_MODEL + h * HEAD_DIM + kc;
            cpa16(ks0 + (uint32_t)(st * FST + row * FS + kc) * 2, K + g);
            cpa16(vs0 + (uint32_t)(st * FST + row * FS + kc) * 2, V + g);
        }
        CP_COMMIT();
    };

    load_q();
    load_kv(0, 0);
    load_kv(1, 1);

    const int rowA = q0 + wid * 16 + gid;
    float qsA, qsB;
    {
        const float4* p0 = (const float4*)&phi[(size_t)(b * SEQ + rowA) * PHI_F];
        const float4* p1 = (const float4*)&phi[(size_t)(b * SEQ + rowA + 8) * PHI_F];
        float4 a0 = p0[0], a1 = p0[1], b0 = p1[0], b1 = p1[1];
        float sA = (a0.x + a0.y + a0.z + a0.w + a1.x + a1.y + a1.z + a1.w) * (1.0f / PHI_F);
        float sB = (b0.x + b0.y + b0.z + b0.w + b1.x + b1.y + b1.z + b1.w) * (1.0f / PHI_F);
        qsA = LOG2E / (8.0f * fmaxf(sA, 1e-6f));
        qsB = LOG2E / (8.0f * fmaxf(sB, 1e-6f));
    }

    float mA = -CUDART_INF_F, mB = -CUDART_INF_F;
    float lA = 0.f, lB = 0.f;          // per-thread partials; reduced once at end
    float o[8][4];
#pragma unroll
    for (int d = 0; d < 8; ++d)
#pragma unroll
        for (int k = 0; k < 4; ++k) o[d][k] = 0.f;

    const int sub = lane >> 3, r = lane & 7;
    const int kRow = ((sub & 2) ? 8 : 0) + r, kCol = (sub & 1) ? 8 : 0;
    const int vRow = ((sub & 1) ? 8 : 0) + r, vCol = (sub & 2) ? 8 : 0;

    CP_WAIT(1);
    __syncthreads();

    uint32_t qf[4][4];
    {
        const int qRow = wid * 16 + ((sub & 1) ? 8 : 0) + r;
        const int qCol = (sub & 2) ? 8 : 0;
        uint32_t base = qs0 + (uint32_t)(qRow * FS + qCol) * 2;
#pragma unroll
        for (int ks = 0; ks < 4; ++ks) ldsm_x4(qf[ks], base + (uint32_t)(ks * 16) * 2);
    }

    for (int kt = 0; kt < FNT; ++kt) {
        const int st = kt % 3;
        if (kt > 0) {
            if (kt < FNT - 1) CP_WAIT(1); else CP_WAIT(0);
            __syncthreads();
        }
        if (kt + 2 < FNT) load_kv(kt + 2, (kt + 2) % 3);

        // ---- S = Q K^T (raw scores) ----
        float s[8][4];
#pragma unroll
        for (int n = 0; n < 8; ++n)
#pragma unroll
            for (int k = 0; k < 4; ++k) s[n][k] = 0.f;

        const uint32_t kBase = ks0 + (uint32_t)(st * FST + kRow * FS + kCol) * 2;
#pragma unroll
        for (int ks = 0; ks < 4; ++ks) {
#pragma unroll
            for (int np = 0; np < 4; ++np) {
                uint32_t bf[4];
                ldsm_x4(bf, kBase + (uint32_t)(np * 16 * FS + ks * 16) * 2);
                mma16816(s[2 * np + 0], qf[ks], bf[0], bf[1]);
                mma16816(s[2 * np + 1], qf[ks], bf[2], bf[3]);
            }
        }

        // ---- online softmax: max on RAW scores (qs > 0 commutes with max) ----
        float tA = -CUDART_INF_F, tB = -CUDART_INF_F;
#pragma unroll
        for (int n = 0; n < 8; ++n) {
            tA = fmaxf(tA, fmaxf(s[n][0], s[n][1]));
            tB = fmaxf(tB, fmaxf(s[n][2], s[n][3]));
        }
        tA = fmaxf(tA, __shfl_xor_sync(0xffffffffu, tA, 1));
        tA = fmaxf(tA, __shfl_xor_sync(0xffffffffu, tA, 2));
        tB = fmaxf(tB, __shfl_xor_sync(0xffffffffu, tB, 1));
        tB = fmaxf(tB, __shfl_xor_sync(0xffffffffu, tB, 2));

        float mAn = fmaxf(mA, tA * qsA), mBn = fmaxf(mB, tB * qsB);
        const bool changed = (mAn > mA) || (mBn > mB);
        if (__any_sync(0xffffffffu, changed)) {
            float cA = ex2(mA - mAn), cB = ex2(mB - mBn);
            mA = mAn; mB = mBn;
            lA *= cA; lB *= cB;
#pragma unroll
            for (int d = 0; d < 8; ++d) {
                o[d][0] *= cA; o[d][1] *= cA;
                o[d][2] *= cB; o[d][3] *= cB;
            }
        }

        // exp2(s*qs - m) via single FFMA + MUFU; local (deferred) row sums
        float sumA = 0.f, sumB = 0.f;
#pragma unroll
        for (int n = 0; n < 8; ++n) {
            s[n][0] = ex2(fmaf(s[n][0], qsA, -mA));
            s[n][1] = ex2(fmaf(s[n][1], qsA, -mA));
            s[n][2] = ex2(fmaf(s[n][2], qsB, -mB));
            s[n][3] = ex2(fmaf(s[n][3], qsB, -mB));
            sumA += s[n][0] + s[n][1];
            sumB += s[n][2] + s[n][3];
        }
        lA += sumA;
        lB += sumB;

        // ---- O += P V ----
        const uint32_t vBase = vs0 + (uint32_t)(st * FST + vRow * FS + vCol) * 2;
#pragma unroll
        for (int ks = 0; ks < 4; ++ks) {
            uint32_t pa[4];
            pa[0] = pack_h2(s[2 * ks][0], s[2 * ks][1]);
            pa[1] = pack_h2(s[2 * ks][2], s[2 * ks][3]);
            pa[2] = pack_h2(s[2 * ks + 1][0], s[2 * ks + 1][1]);
            pa[3] = pack_h2(s[2 * ks + 1][2], s[2 * ks + 1][3]);
#pragma unroll
            for (int dp = 0; dp < 4; ++dp) {
                uint32_t bf[4];
                ldsm_x4_t(bf, vBase + (uint32_t)(ks * 16 * FS + dp * 16) * 2);
                mma16816(o[2 * dp + 0], pa, bf[0], bf[1]);
                mma16816(o[2 * dp + 1], pa, bf[2], bf[3]);
            }
        }
    }

    // deferred cross-thread reduction of l (quad shares the same m-frame)
    lA += __shfl_xor_sync(0xffffffffu, lA, 1);
    lA += __shfl_xor_sync(0xffffffffu, lA, 2);
    lB += __shfl_xor_sync(0xffffffffu, lB, 1);
    lB += __shfl_xor_sync(0xffffffffu, lB, 2);

    const float iA = 1.0f / lA, iB = 1.0f / lB;
#pragma unroll
    for (int d = 0; d < 8; ++d) {
        int col = h * HEAD_DIM + d * 8 + 2 * tig;
        __half2* p0 = (__half2*)(O + (size_t)(b * SEQ + rowA) * D_MODEL + col);
        __half2* p1 = (__half2*)(O + (size_t)(b * SEQ + rowA + 8) * D_MODEL + col);
        *p0 = __floats2half2_rn(o[d][0] * iA, o[d][1] * iA);
        *p1 = __floats2half2_rn(o[d][2] * iB, o[d][3] * iB);
    }
}

// ---------------- launch ------------------------------------------------------
extern "C" void kernel_launch(void* const* d_in, const int* in_sizes, int n_in,
                              void* d_out, int out_size) {
    const float* query = (const float*)d_in[0];
    const float* key   = (const float*)d_in[1];
    const float* value = (const float*)d_in[2];
    const float* phi   = (const float*)d_in[3];
    const float* Wq = (const float*)d_in[5];
    const float* bq = (const float*)d_in[6];
    const float* Wk = (const float*)d_in[7];
    const float* bk = (const float*)d_in[8];
    const float* Wv = (const float*)d_in[9];
    const float* bv = (const float*)d_in[10];
    const float* Wo = (const float*)d_in[11];
    const float* bo = (const float*)d_in[12];
    float* out = (float*)d_out;

    __half *hA, *hB, *hC, *hWq, *hWk, *hWv, *hWo, *hq, *hk, *hv, *hattn;
    cudaGetSymbolAddress((void**)&hA, g_hA);
    cudaGetSymbolAddress((void**)&hB, g_hB);
    cudaGetSymbolAddress((void**)&hC, g_hC);
    cudaGetSymbolAddress((void**)&hWq, g_hWq);
    cudaGetSymbolAddress((void**)&hWk, g_hWk);
    cudaGetSymbolAddress((void**)&hWv, g_hWv);
    cudaGetSymbolAddress((void**)&hWo, g_hWo);
    cudaGetSymbolAddress((void**)&hq, g_hq);
    cudaGetSymbolAddress((void**)&hk, g_hk);
    cudaGetSymbolAddress((void**)&hv, g_hv);
    cudaGetSymbolAddress((void**)&hattn, g_hattn);

    cudaFuncSetAttribute(gemm_qkv, cudaFuncAttributeMaxDynamicSharedMemorySize, G_SMEM);
    cudaFuncSetAttribute(gemm_out, cudaFuncAttributeMaxDynamicSharedMemorySize, G_SMEM);
    cudaFuncSetAttribute(flash_h, cudaFuncAttributeMaxDynamicSharedMemorySize, F_SMEM);

    const int nW8 = D_MODEL * D_MODEL / 8;   // 131072
    const int nA8 = MTOT * D_MODEL / 8;      // 524288

    f2h7<<<dim3((nA8 + 255) / 256, 7), 256>>>(
        (const float4*)Wq, (const float4*)Wk, (const float4*)Wv, (const float4*)Wo,
        (const float4*)query, (const float4*)key, (const float4*)value,
        (uint4*)hWq, (uint4*)hWk, (uint4*)hWv, (uint4*)hWo,
        (uint4*)hA, (uint4*)hB, (uint4*)hC, nW8, nA8);

    dim3 qkvgrid(D_MODEL / 128, MTOT / 128, 3);
    gemm_qkv<<<qkvgrid, 256, G_SMEM>>>(hA, hB, hC, hWq, hWk, hWv, bq, bk, bv, hq, hk, hv);

    dim3 fgrid(SEQ / FBQ, NUM_HEADS, BATCH);
    flash_h<<<fgrid, 256, F_SMEM>>>(hq, hk, hv, phi, hattn);

    dim3 ggrid(D_MODEL / 128, MTOT / 128);
    gemm_out<<<ggrid, 256, G_SMEM>>>(hattn, hWo, bo, out);
}